// round 12
// baseline (speedup 1.0000x reference)
#include <cuda_runtime.h>
#include <math.h>

#define Bsz   2048
#define Fdim  128
#define Hdim  512
#define Tlen  96
#define G3H   1536
#define Mtile 16
#define NTHREADS 256

typedef unsigned long long ull;
typedef ulonglong2 ull2;

// Transposed weights (k-major) in device scratch, ~4MB, L2-resident.
__device__ __align__(16) float d_WhhT[Hdim * G3H];  // [k][n] k<512, n<1536
__device__ __align__(16) float d_WihT[Fdim * G3H];  // [k][n] k<128, n<1536
__device__ __align__(16) float d_FcwT[Hdim * Fdim]; // [k][f] k<512, f<128

// ---- packed f32x2 helpers ----
__device__ __forceinline__ ull bcast2(float a) {
    ull r; unsigned int u = __float_as_uint(a);
    asm("mov.b64 %0, {%1, %1};" : "=l"(r) : "r"(u));
    return r;
}
__device__ __forceinline__ void fma2(ull& d, ull a, ull b) {
    asm("fma.rn.f32x2 %0, %1, %2, %0;" : "+l"(d) : "l"(a), "l"(b));
}
__device__ __forceinline__ float2 unpack2(ull v) {
    unsigned int lo, hi;
    asm("mov.b64 {%0, %1}, %2;" : "=r"(lo), "=r"(hi) : "l"(v));
    return make_float2(__uint_as_float(lo), __uint_as_float(hi));
}
__device__ __forceinline__ ull ld64(const float* p) {
    return *reinterpret_cast<const ull*>(p);
}
__device__ __forceinline__ float fast_sigmoid(float x) {
    return __fdividef(1.f, 1.f + __expf(-x));
}
__device__ __forceinline__ float fast_tanh(float x) {
    float t = __expf(2.f * x);
    return 1.f - __fdividef(2.f, t + 1.f);
}

// One-time weight transpose
__global__ void gru_setup_kernel(const float* __restrict__ w_ih,
                                 const float* __restrict__ w_hh,
                                 const float* __restrict__ fc_w) {
    int idx = blockIdx.x * blockDim.x + threadIdx.x;
    if (idx < Hdim * G3H) {
        int k = idx / G3H, n = idx - k * G3H;
        d_WhhT[idx] = w_hh[n * Hdim + k];
    }
    int i2 = idx - Hdim * G3H;
    if (i2 >= 0 && i2 < Fdim * G3H) {
        int k = i2 / G3H, n = i2 - k * G3H;
        d_WihT[i2] = w_ih[n * Fdim + k];
    }
    int i3 = idx - Hdim * G3H - Fdim * G3H;
    if (i3 >= 0 && i3 < Hdim * Fdim) {
        int k = i3 / Fdim, f = i3 - k * Fdim;
        d_FcwT[i3] = fc_w[f * Hdim + k];
    }
}

// Load one 2-kk weight stage: 3 gates x 4 cols per kk (ld128 each).
__device__ __forceinline__ void ldw3(ull2 (&wb)[2][3], const float* wk, int stage) {
    const float* p = wk + (size_t)stage * 2 * G3H;
    #pragma unroll
    for (int kk = 0; kk < 2; ++kk) {
        const float* q = p + (size_t)kk * G3H;
        wb[kk][0] = *reinterpret_cast<const ull2*>(q);
        wb[kk][1] = *reinterpret_cast<const ull2*>(q + 512);
        wb[kk][2] = *reinterpret_cast<const ull2*>(q + 1024);
    }
}

// Compute one 2-kk stage: 8 m-rows x 4 n-cols x 3 gates.
template<int LD>
__device__ __forceinline__ void g3_stage(
    const ull2 (&w)[2][3], const float* __restrict__ in, int k0, int m0,
    ull (&aR)[8][2], ull (&aZ)[8][2], ull (&aX)[8][2])
{
    float2 av[8];
    #pragma unroll
    for (int m = 0; m < 8; ++m)
        av[m] = *reinterpret_cast<const float2*>(&in[(m0 + m) * LD + k0]);
    #pragma unroll
    for (int kk = 0; kk < 2; ++kk) {
        #pragma unroll
        for (int m = 0; m < 8; ++m) {
            ull a2 = bcast2(kk ? av[m].y : av[m].x);
            fma2(aR[m][0], a2, w[kk][0].x); fma2(aR[m][1], a2, w[kk][0].y);
            fma2(aZ[m][0], a2, w[kk][1].x); fma2(aZ[m][1], a2, w[kk][1].y);
            fma2(aX[m][0], a2, w[kk][2].x); fma2(aX[m][1], a2, w[kk][2].y);
        }
    }
}

// Split-K 3-gate GEMM over this thread's K-slice, register A/B ping-pong.
template<int LD, int NST>   // NST = K_slice/2, even
__device__ __forceinline__ void gemm3_split(
    const float* __restrict__ wbase,   // WT + colbase
    const float* __restrict__ in, int kbeg, int m0,
    ull (&aR)[8][2], ull (&aZ)[8][2], ull (&aX)[8][2])
{
    ull2 wA[2][3], wB[2][3];
    const float* wk = wbase + (size_t)kbeg * G3H;
    ldw3(wA, wk, 0);
    #pragma unroll 1
    for (int it = 0; it < NST; it += 2) {
        ldw3(wB, wk, it + 1);
        g3_stage<LD>(wA, in, kbeg + it * 2, m0, aR, aZ, aX);
        ldw3(wA, wk, (it + 2 < NST) ? it + 2 : it);
        g3_stage<LD>(wB, in, kbeg + (it + 1) * 2, m0, aR, aZ, aX);
    }
}

// ---- fc GEMM (phase 2), 16m x 2f per thread, split-K ----
__device__ __forceinline__ void gf_stage(
    const ull (&w)[4], const float* __restrict__ in, int k0, ull (&aF)[16])
{
    float2 av[16];
    #pragma unroll
    for (int m = 0; m < 16; ++m)
        av[m] = *reinterpret_cast<const float2*>(&in[m * Hdim + k0]);
    #pragma unroll
    for (int kk = 0; kk < 2; ++kk) {
        #pragma unroll
        for (int m = 0; m < 16; ++m)
            fma2(aF[m], bcast2(kk ? av[m].y : av[m].x), w[kk]);
    }
    #pragma unroll
    for (int m = 0; m < 16; ++m)
        av[m] = *reinterpret_cast<const float2*>(&in[m * Hdim + k0 + 2]);
    #pragma unroll
    for (int kk = 2; kk < 4; ++kk) {
        #pragma unroll
        for (int m = 0; m < 16; ++m)
            fma2(aF[m], bcast2((kk & 1) ? av[m].y : av[m].x), w[kk]);
    }
}

template<int NST>
__device__ __forceinline__ void gemmF_split(
    const float* __restrict__ wbase, const float* __restrict__ in,
    int kbeg, ull (&aF)[16])
{
    ull wA[4], wB[4];
    const float* wk = wbase + (size_t)kbeg * Fdim;
    #pragma unroll
    for (int kk = 0; kk < 4; ++kk) wA[kk] = ld64(wk + (size_t)kk * Fdim);
    #pragma unroll 1
    for (int it = 0; it < NST; it += 2) {
        #pragma unroll
        for (int kk = 0; kk < 4; ++kk)
            wB[kk] = ld64(wk + (size_t)((it + 1) * 4 + kk) * Fdim);
        gf_stage(wA, in, kbeg + it * 4, aF);
        {
            const int nx = (it + 2 < NST) ? (it + 2) : it;
            #pragma unroll
            for (int kk = 0; kk < 4; ++kk)
                wA[kk] = ld64(wk + (size_t)(nx * 4 + kk) * Fdim);
        }
        gf_stage(wB, in, kbeg + (it + 1) * 4, aF);
    }
}

__global__ __launch_bounds__(NTHREADS, 1)
void gru_kernel(const float* __restrict__ hidden,
                const float* __restrict__ b_ih,
                const float* __restrict__ b_hh,
                const float* __restrict__ fc_b,
                float* __restrict__ out) {
    extern __shared__ float smem[];
    float* hbufA = smem;                          // 16*512
    float* hbufB = hbufA + Mtile * Hdim;          // 16*512
    float* xbuf  = hbufB + Mtile * Hdim;          // 16*128
    float* brz   = xbuf + Mtile * Fdim;           // 1024
    float* bin   = brz + 2 * Hdim;                // 512
    float* bhn   = bin + Hdim;                    // 512
    float* fcb   = bhn + Hdim;                    // 128
    float* part  = fcb + Fdim;                    // 16 slots * 16 m * 128 cols

    const int tid = threadIdx.x;
    const int m0cta = blockIdx.x * Mtile;

    for (int i = tid; i < Mtile * Hdim; i += NTHREADS) hbufA[i] = hidden[m0cta * Hdim + i];
    for (int i = tid; i < Mtile * Fdim; i += NTHREADS) xbuf[i] = 0.f;
    for (int i = tid; i < 2 * Hdim; i += NTHREADS)     brz[i] = b_ih[i] + b_hh[i];
    for (int i = tid; i < Hdim; i += NTHREADS) {
        bin[i] = b_ih[2 * Hdim + i];
        bhn[i] = b_hh[2 * Hdim + i];
    }
    for (int i = tid; i < Fdim; i += NTHREADS)         fcb[i] = fc_b[i];
    __syncthreads();

    // Phase-1 mapping: [2 mg][4 kg][32 ng4]
    const int mg   = tid >> 7;            // 0..1
    const int kg   = (tid >> 5) & 3;      // 0..3
    const int ng4  = tid & 31;            // 0..31
    const int col4 = ng4 * 4;
    const int m0   = mg * 8;
    const int khh  = kg * 128;
    const int kih  = kg * 32;
    // Epilogue / phase-2 mapping: [4 groups of 4 m][64 ng2]
    const int mg4  = (tid >> 6) * 4;
    const int ng2  = (tid & 63) * 2;
    const int kg2  = tid >> 6;            // phase-2 K-slice group

    float* hc = hbufA;
    float* hn = hbufB;

    for (int s = 0; s < Tlen; ++s) {
        // ===== Phase 1: gates + h update, 4 chunks of 128 n-cols per gate =====
        #pragma unroll 1
        for (int nc = 0; nc < 4; ++nc) {
            const int colbase = nc * 128 + col4;

            ull aR[8][2], aZ[8][2], aX[8][2];
            #pragma unroll
            for (int m = 0; m < 8; ++m) {
                aR[m][0] = 0; aR[m][1] = 0; aZ[m][0] = 0; aZ[m][1] = 0;
                aX[m][0] = 0; aX[m][1] = 0;
            }

            // ih contribution first: k in [kg*32, kg*32+32)
            gemm3_split<Fdim, 16>(d_WihT + colbase, xbuf, kih, m0, aR, aZ, aX);

            // dump i_n partials; keep r/z live in registers
            #pragma unroll
            for (int m = 0; m < 8; ++m) {
                ull2 v; v.x = aX[m][0]; v.y = aX[m][1];
                *reinterpret_cast<ull2*>(
                    &part[((12 + kg) * 16 + m0 + m) * 128 + col4]) = v;
                aX[m][0] = 0; aX[m][1] = 0;
            }

            // hh contribution: k in [kg*128, kg*128+128)
            gemm3_split<Hdim, 64>(d_WhhT + colbase, hc, khh, m0, aR, aZ, aX);

            // dump r, z, h_n partials
            #pragma unroll
            for (int m = 0; m < 8; ++m) {
                ull2 v;
                v.x = aR[m][0]; v.y = aR[m][1];
                *reinterpret_cast<ull2*>(&part[((kg)     * 16 + m0 + m) * 128 + col4]) = v;
                v.x = aZ[m][0]; v.y = aZ[m][1];
                *reinterpret_cast<ull2*>(&part[((4 + kg) * 16 + m0 + m) * 128 + col4]) = v;
                v.x = aX[m][0]; v.y = aX[m][1];
                *reinterpret_cast<ull2*>(&part[((8 + kg) * 16 + m0 + m) * 128 + col4]) = v;
            }
            __syncthreads();

            // epilogue: reduce 4 kg slices, apply gates; 4 m x 2 cols per thread
            const int col = nc * 128 + ng2;
            const float2 br = *reinterpret_cast<const float2*>(&brz[col]);
            const float2 bz = *reinterpret_cast<const float2*>(&brz[Hdim + col]);
            const float2 bi = *reinterpret_cast<const float2*>(&bin[col]);
            const float2 bh = *reinterpret_cast<const float2*>(&bhn[col]);
            #pragma unroll
            for (int i = 0; i < 4; ++i) {
                const int m = mg4 + i;
                float2 R = make_float2(0.f, 0.f), Z = R, NH = R, NI = R;
                #pragma unroll
                for (int g = 0; g < 4; ++g) {
                    float2 v;
                    v = *reinterpret_cast<const float2*>(&part[((g)      * 16 + m) * 128 + ng2]);
                    R.x += v.x; R.y += v.y;
                    v = *reinterpret_cast<const float2*>(&part[((4 + g)  * 16 + m) * 128 + ng2]);
                    Z.x += v.x; Z.y += v.y;
                    v = *reinterpret_cast<const float2*>(&part[((8 + g)  * 16 + m) * 128 + ng2]);
                    NH.x += v.x; NH.y += v.y;
                    v = *reinterpret_cast<const float2*>(&part[((12 + g) * 16 + m) * 128 + ng2]);
                    NI.x += v.x; NI.y += v.y;
                }
                float2 hp = *reinterpret_cast<const float2*>(&hc[m * Hdim + col]);
                float r0 = fast_sigmoid(R.x + br.x);
                float r1 = fast_sigmoid(R.y + br.y);
                float z0 = fast_sigmoid(Z.x + bz.x);
                float z1 = fast_sigmoid(Z.y + bz.y);
                float n0 = fast_tanh(NI.x + bi.x + r0 * (NH.x + bh.x));
                float n1 = fast_tanh(NI.y + bi.y + r1 * (NH.y + bh.y));
                *reinterpret_cast<float2*>(&hn[m * Hdim + col]) =
                    make_float2((1.f - z0) * n0 + z0 * hp.x,
                                (1.f - z1) * n1 + z1 * hp.y);
            }
            __syncthreads();   // partials consumed; hn chunk visible
        }

        // ===== Phase 2: x_new = h_new @ fc_w^T + fc_b (split-K) =====
        {
            ull aF[16];
            #pragma unroll
            for (int m = 0; m < 16; ++m) aF[m] = 0;
            gemmF_split<32>(d_FcwT + ng2, hn, kg2 * 128, aF);

            #pragma unroll
            for (int m = 0; m < 16; ++m)
                *reinterpret_cast<ull*>(&part[(kg2 * 16 + m) * 128 + ng2]) = aF[m];
            __syncthreads();

            const int trow = Tlen - 1 - s;   // reference reverses time at the end
            const float2 fb2 = *reinterpret_cast<const float2*>(&fcb[ng2]);
            #pragma unroll
            for (int i = 0; i < 4; ++i) {
                const int m = mg4 + i;
                float2 F = make_float2(0.f, 0.f);
                #pragma unroll
                for (int g = 0; g < 4; ++g) {
                    float2 v = *reinterpret_cast<const float2*>(
                        &part[(g * 16 + m) * 128 + ng2]);
                    F.x += v.x; F.y += v.y;
                }
                const float v0 = F.x + fb2.x;
                const float v1 = F.y + fb2.y;
                *reinterpret_cast<float2*>(&xbuf[m * Fdim + ng2]) = make_float2(v0, v1);
                *reinterpret_cast<float2*>(
                    &out[((size_t)(m0cta + m) * Tlen + trow) * Fdim + ng2]) =
                    make_float2(v0, v1);
            }
            __syncthreads();
        }

        float* tmp = hc; hc = hn; hn = tmp;
    }
}

extern "C" void kernel_launch(void* const* d_in, const int* in_sizes, int n_in,
                              void* d_out, int out_size) {
    const float* hidden = (const float*)d_in[0];
    const float* w_ih   = (const float*)d_in[1];
    const float* w_hh   = (const float*)d_in[2];
    const float* b_ih   = (const float*)d_in[3];
    const float* b_hh   = (const float*)d_in[4];
    const float* fc_w   = (const float*)d_in[5];
    const float* fc_b   = (const float*)d_in[6];
    float* out = (float*)d_out;

    const int total = Hdim * G3H + Fdim * G3H + Hdim * Fdim;
    gru_setup_kernel<<<(total + 255) / 256, 256>>>(w_ih, w_hh, fc_w);

    const int smem_floats =
        2 * Mtile * Hdim + Mtile * Fdim + 2 * Hdim + Hdim + Hdim + Fdim +
        16 * 16 * 128;
    const int smem_bytes = smem_floats * (int)sizeof(float);
    cudaFuncSetAttribute(gru_kernel, cudaFuncAttributeMaxDynamicSharedMemorySize, smem_bytes);
    gru_kernel<<<Bsz / Mtile, NTHREADS, smem_bytes>>>(hidden, b_ih, b_hh, fc_b, out);
}

// round 15
// speedup vs baseline: 1.8918x; 1.8918x over previous
#include <cuda_runtime.h>
#include <cuda_bf16.h>
#include <stdint.h>

#define Tlen 96
#define NTH  256

// Pre-swizzled bf16 hi/lo tiles in device scratch (L2-resident).
// Wg : [cb][gate(r,z,n)][hl][chunk<10] {64n x 64k}  (chunks 0-7 = w_hh k, 8-9 = w_ih k)
// Wf : [cb][hl][chunk<8] {16n x 64k}
// Act: [buf][mb][hl][chunk<10] {128m x 64k}         (chunks 0-7 = h, 8-9 = x)
__device__ __align__(16) __nv_bfloat16 d_Wg[8][3][2][10][4096];
__device__ __align__(16) __nv_bfloat16 d_Wf[8][2][8][1024];
__device__ __align__(16) __nv_bfloat16 d_Act[2][16][2][10][8192];
__device__ unsigned int d_bar;

// Tile layout: row-major rows of 64 bf16 (128B), 16B units xor-swizzled by row
// (unit' = unit ^ (row&7)) so ldmatrix is bank-conflict-free.
__host__ __device__ __forceinline__ int tile_off(int row, int kk) {
    int unit = (kk >> 3) ^ (row & 7);
    return row * 128 + (unit << 4) + (kk & 7) * 2;
}
__device__ __forceinline__ void bsplit(float f, __nv_bfloat16& hi, __nv_bfloat16& lo) {
    hi = __float2bfloat16(f);
    lo = __float2bfloat16(f - __bfloat162float(hi));
}
__device__ __forceinline__ uint32_t smem_u32(const void* p) {
    uint32_t a;
    asm("{ .reg .u64 t; cvta.to.shared.u64 t, %1; cvt.u32.u64 %0, t; }" : "=r"(a) : "l"(p));
    return a;
}
__device__ __forceinline__ void cpa16(uint32_t dst, const void* src) {
    asm volatile("cp.async.cg.shared.global [%0], [%1], 16;" :: "r"(dst), "l"(src));
}
#define CP_COMMIT() asm volatile("cp.async.commit_group;" ::: "memory")
#define CP_WAIT1()  asm volatile("cp.async.wait_group 1;" ::: "memory")
#define CP_WAIT0()  asm volatile("cp.async.wait_group 0;" ::: "memory")

__device__ __forceinline__ void ldsm4(uint32_t* r, uint32_t a) {
    asm volatile("ldmatrix.sync.aligned.m8n8.x4.shared.b16 {%0,%1,%2,%3}, [%4];"
        : "=r"(r[0]), "=r"(r[1]), "=r"(r[2]), "=r"(r[3]) : "r"(a));
}
__device__ __forceinline__ void mmabf(float* d, const uint32_t* a, const uint32_t* b) {
    asm volatile("mma.sync.aligned.m16n8k16.row.col.f32.bf16.bf16.f32 "
        "{%0,%1,%2,%3},{%4,%5,%6,%7},{%8,%9},{%0,%1,%2,%3};"
        : "+f"(d[0]), "+f"(d[1]), "+f"(d[2]), "+f"(d[3])
        : "r"(a[0]), "r"(a[1]), "r"(a[2]), "r"(a[3]), "r"(b[0]), "r"(b[1]));
}
// A fragment (m16 x k16) address for this lane; regs = (m0-7,k0-7),(m8-15,k0-7),(m0-7,k8-15),(m8-15,k8-15)
__device__ __forceinline__ uint32_t a_addr(uint32_t base, int mrow, int q, int lane) {
    int row = mrow + ((lane >> 3) & 1) * 8 + (lane & 7);
    int unit = 2 * q + (lane >> 4);
    return base + row * 128 + ((unit ^ (row & 7)) << 4);
}
// B fragments: one x4 covers 2 n8 tiles x k16: regs = (n0-7,k0-7),(n0-7,k8-15),(n8-15,k0-7),(n8-15,k8-15)
__device__ __forceinline__ uint32_t b_addr(uint32_t base, int nbase, int q, int lane) {
    int nrow = nbase + ((lane >> 4) << 3) + (lane & 7);
    int unit = 2 * q + ((lane >> 3) & 1);
    return base + nrow * 128 + ((unit ^ (nrow & 7)) << 4);
}

__device__ __forceinline__ float sigm(float x) { return __fdividef(1.f, 1.f + __expf(-x)); }
__device__ __forceinline__ float ftanh(float x) {
    float t = __expf(2.f * x);
    return 1.f - __fdividef(2.f, t + 1.f);
}
__device__ __forceinline__ void grid_sync(unsigned tgt) {
    __threadfence();
    __syncthreads();
    if (threadIdx.x == 0) {
        atomicAdd(&d_bar, 1u);
        while (((volatile unsigned int*)&d_bar)[0] < tgt) __nanosleep(32);
    }
    __syncthreads();
    __threadfence();
}

// ---------------- setup kernels ----------------
__global__ void setup_weights(const float* __restrict__ w_ih,
                              const float* __restrict__ w_hh,
                              const float* __restrict__ fc_w) {
    const int N1 = 8 * 3 * 10 * 4096, N2 = 8 * 8 * 1024;
    for (int idx = blockIdx.x * blockDim.x + threadIdx.x; idx < N1 + N2;
         idx += gridDim.x * blockDim.x) {
        if (idx < N1) {
            int cb = idx / (3 * 10 * 4096), r = idx % (3 * 10 * 4096);
            int g = r / (10 * 4096); r %= 10 * 4096;
            int c = r / 4096, e = r % 4096;
            int j = e >> 6, kk = e & 63;
            int n = g * 512 + cb * 64 + j;
            float f = (c < 8) ? w_hh[n * 512 + c * 64 + kk]
                              : w_ih[n * 128 + (c - 8) * 64 + kk];
            __nv_bfloat16 hi, lo; bsplit(f, hi, lo);
            int to = tile_off(j, kk);
            *(__nv_bfloat16*)((char*)&d_Wg[cb][g][0][c][0] + to) = hi;
            *(__nv_bfloat16*)((char*)&d_Wg[cb][g][1][c][0] + to) = lo;
        } else {
            int i2 = idx - N1;
            int cb = i2 / (8 * 1024), r = i2 % (8 * 1024);
            int c = r / 1024, e = r % 1024;
            int j = e >> 6, kk = e & 63;
            float f = fc_w[(cb * 16 + j) * 512 + c * 64 + kk];
            __nv_bfloat16 hi, lo; bsplit(f, hi, lo);
            int to = tile_off(j, kk);
            *(__nv_bfloat16*)((char*)&d_Wf[cb][0][c][0] + to) = hi;
            *(__nv_bfloat16*)((char*)&d_Wf[cb][1][c][0] + to) = lo;
        }
    }
}

__global__ void setup_state(const float* __restrict__ hidden) {
    const int N1 = 2048 * 512, N2 = 16 * 2 * 2 * 8192;
    for (int idx = blockIdx.x * blockDim.x + threadIdx.x; idx < N1 + N2;
         idx += gridDim.x * blockDim.x) {
        if (idx < N1) {
            int row = idx >> 9, col = idx & 511;
            int mb = row >> 7, m = row & 127, c = col >> 6, kk = col & 63;
            __nv_bfloat16 hi, lo; bsplit(hidden[idx], hi, lo);
            int to = tile_off(m, kk);
            *(__nv_bfloat16*)((char*)&d_Act[0][mb][0][c][0] + to) = hi;
            *(__nv_bfloat16*)((char*)&d_Act[0][mb][1][c][0] + to) = lo;
        } else {
            int i2 = idx - N1;
            int mb = i2 / (2 * 2 * 8192), r = i2 % (2 * 2 * 8192);
            int hl = r / (2 * 8192); r %= 2 * 8192;
            int c8 = r / 8192, e = r % 8192;
            d_Act[0][mb][hl][8 + c8][e] = __float2bfloat16(0.f);
        }
    }
    if (blockIdx.x == 0 && threadIdx.x == 0) d_bar = 0;
}

// ---------------- main persistent kernel ----------------
// smem: [64..1152) biases; A bufs @2048 (2 x 32KB: hi 16K + lo 16K);
//       B bufs @67584 (2 x 48KB: r_hi,r_lo,z_hi,z_lo,n_hi,n_lo @ 8KB each).
#define SM_A  2048
#define SM_B  67584
#define SMTOT 165888

// One gate's n32 slice for one k16: 3-product mma into acc.
__device__ __forceinline__ void process_gate(
    uint32_t Bg, int lane, int wn32, int q,
    const uint32_t ah[2][4], const uint32_t al[2][4], float (*acc)[4][4])
{
    uint32_t b0[4], b1[4];
    ldsm4(b0, b_addr(Bg, wn32, q, lane));        // hi: tiles nt0, nt1
    ldsm4(b1, b_addr(Bg, wn32 + 16, q, lane));   // hi: tiles nt2, nt3
    #pragma unroll
    for (int mb2 = 0; mb2 < 2; ++mb2) {
        mmabf(acc[mb2][0], ah[mb2], b0);     mmabf(acc[mb2][1], ah[mb2], b0 + 2);
        mmabf(acc[mb2][2], ah[mb2], b1);     mmabf(acc[mb2][3], ah[mb2], b1 + 2);
        mmabf(acc[mb2][0], al[mb2], b0);     mmabf(acc[mb2][1], al[mb2], b0 + 2);
        mmabf(acc[mb2][2], al[mb2], b1);     mmabf(acc[mb2][3], al[mb2], b1 + 2);
    }
    ldsm4(b0, b_addr(Bg + 8192, wn32, q, lane));        // lo
    ldsm4(b1, b_addr(Bg + 8192, wn32 + 16, q, lane));
    #pragma unroll
    for (int mb2 = 0; mb2 < 2; ++mb2) {
        mmabf(acc[mb2][0], ah[mb2], b0);     mmabf(acc[mb2][1], ah[mb2], b0 + 2);
        mmabf(acc[mb2][2], ah[mb2], b1);     mmabf(acc[mb2][3], ah[mb2], b1 + 2);
    }
}

__global__ __launch_bounds__(NTH, 1)
void gru_main(const float* __restrict__ b_ih, const float* __restrict__ b_hh,
              const float* __restrict__ fc_b, float* __restrict__ out) {
    extern __shared__ char sm[];
    const uint32_t smb = smem_u32(sm);
    const int tid = threadIdx.x;
    const int wid = tid >> 5, lane = tid & 31;
    const int mb = blockIdx.x >> 3, cb = blockIdx.x & 7;
    const int wm32 = (wid & 3) * 32;   // warp m-rows
    const int wn32 = (wid >> 2) * 32;  // warp gate-cols (j)

    float* s_br = (float*)(sm + 64);
    float* s_bz = s_br + 64;
    float* s_bi = s_bz + 64;
    float* s_bh = s_bi + 64;
    float* s_fb = s_bh + 64;
    if (tid < 64) {
        s_br[tid] = b_ih[cb * 64 + tid] + b_hh[cb * 64 + tid];
        s_bz[tid] = b_ih[512 + cb * 64 + tid] + b_hh[512 + cb * 64 + tid];
        s_bi[tid] = b_ih[1024 + cb * 64 + tid];
        s_bh[tid] = b_hh[1024 + cb * 64 + tid];
    }
    if (tid < 16) s_fb[tid] = fc_b[cb * 16 + tid];
    __syncthreads();

    unsigned tgt = 0;

    for (int s = 0; s < Tlen; ++s) {
        const int cur = s & 1, nxt = cur ^ 1;

        // ===== gates: [128 x (r64|z64|n64)] over K=640, 10 chunks, dbl-buffered =====
        float aR[2][4][4], aZ[2][4][4], aN[2][4][4], aI[2][4][4];
        #pragma unroll
        for (int i = 0; i < 2; ++i)
            #pragma unroll
            for (int t = 0; t < 4; ++t)
                #pragma unroll
                for (int k = 0; k < 4; ++k) {
                    aR[i][t][k] = 0.f; aZ[i][t][k] = 0.f;
                    aN[i][t][k] = 0.f; aI[i][t][k] = 0.f;
                }

        // stage chunk helper (lambda-less, inline twice)
        #define STAGE_GATE(c, b) do {                                              \
            const char* Ah_ = (const char*)&d_Act[cur][mb][0][(c)][0];             \
            const char* Al_ = (const char*)&d_Act[cur][mb][1][(c)][0];             \
            uint32_t AB_ = smb + SM_A + (b) * 32768;                               \
            _Pragma("unroll")                                                      \
            for (int r_ = 0; r_ < 4; ++r_) {                                       \
                int u_ = tid + r_ * NTH;                                           \
                cpa16(AB_ + u_ * 16, Ah_ + u_ * 16);                               \
                cpa16(AB_ + 16384 + u_ * 16, Al_ + u_ * 16);                       \
            }                                                                      \
            uint32_t BB_ = smb + SM_B + (b) * 49152;                               \
            _Pragma("unroll")                                                      \
            for (int t_ = 0; t_ < 6; ++t_) {                                       \
                const char* src_ = (const char*)&d_Wg[cb][t_ >> 1][t_ & 1][(c)][0];\
                uint32_t dst_ = BB_ + (t_ >> 1) * 16384 + (t_ & 1) * 8192;         \
                _Pragma("unroll")                                                  \
                for (int r_ = 0; r_ < 2; ++r_) {                                   \
                    int u_ = tid + r_ * NTH;                                       \
                    cpa16(dst_ + u_ * 16, src_ + u_ * 16);                         \
                }                                                                  \
            }                                                                      \
        } while (0)

        STAGE_GATE(0, 0);
        CP_COMMIT();
        #pragma unroll 1
        for (int c = 0; c < 10; ++c) {
            if (c < 9) { STAGE_GATE(c + 1, (c + 1) & 1); CP_COMMIT(); CP_WAIT1(); }
            else       { CP_WAIT0(); }
            __syncthreads();
            const uint32_t AB = smb + SM_A + (c & 1) * 32768;
            const uint32_t BB = smb + SM_B + (c & 1) * 49152;
            float (*aX)[4][4] = (c < 8) ? aN : aI;
            #pragma unroll
            for (int q = 0; q < 4; ++q) {
                uint32_t ah[2][4], al[2][4];
                ldsm4(ah[0], a_addr(AB, wm32, q, lane));
                ldsm4(ah[1], a_addr(AB, wm32 + 16, q, lane));
                ldsm4(al[0], a_addr(AB + 16384, wm32, q, lane));
                ldsm4(al[1], a_addr(AB + 16384, wm32 + 16, q, lane));
                process_gate(BB,         lane, wn32, q, ah, al, aR);
                process_gate(BB + 16384, lane, wn32, q, ah, al, aZ);
                process_gate(BB + 32768, lane, wn32, q, ah, al, aX);
            }
            __syncthreads();
        }

        // ===== gates epilogue: h_new for cols cb*64 + [0,64) (register-local) =====
        {
            const char* hiC = (const char*)&d_Act[cur][mb][0][cb][0];
            const char* loC = (const char*)&d_Act[cur][mb][1][cb][0];
            char* hiN = (char*)&d_Act[nxt][mb][0][cb][0];
            char* loN = (char*)&d_Act[nxt][mb][1][cb][0];
            #pragma unroll
            for (int mb2 = 0; mb2 < 2; ++mb2)
                #pragma unroll
                for (int nt = 0; nt < 4; ++nt) {
                    const int jj = wn32 + nt * 8 + 2 * (lane & 3);
                    #pragma unroll
                    for (int ms = 0; ms < 2; ++ms) {
                        const int m_ = wm32 + mb2 * 16 + (lane >> 2) + ms * 8;
                        const int eo = tile_off(m_, jj);
                        __nv_bfloat162 oh = *(const __nv_bfloat162*)(hiC + eo);
                        __nv_bfloat162 ol = *(const __nv_bfloat162*)(loC + eo);
                        float hp0 = __bfloat162float(oh.x) + __bfloat162float(ol.x);
                        float hp1 = __bfloat162float(oh.y) + __bfloat162float(ol.y);
                        float r0 = sigm(aR[mb2][nt][ms * 2]     + s_br[jj]);
                        float r1 = sigm(aR[mb2][nt][ms * 2 + 1] + s_br[jj + 1]);
                        float z0 = sigm(aZ[mb2][nt][ms * 2]     + s_bz[jj]);
                        float z1 = sigm(aZ[mb2][nt][ms * 2 + 1] + s_bz[jj + 1]);
                        float n0 = ftanh(aI[mb2][nt][ms * 2]     + s_bi[jj] +
                                         r0 * (aN[mb2][nt][ms * 2]     + s_bh[jj]));
                        float n1 = ftanh(aI[mb2][nt][ms * 2 + 1] + s_bi[jj + 1] +
                                         r1 * (aN[mb2][nt][ms * 2 + 1] + s_bh[jj + 1]));
                        float h0 = (1.f - z0) * n0 + z0 * hp0;
                        float h1 = (1.f - z1) * n1 + z1 * hp1;
                        __nv_bfloat16 q0, l0, q1, l1;
                        bsplit(h0, q0, l0); bsplit(h1, q1, l1);
                        __nv_bfloat162 vh; vh.x = q0; vh.y = q1;
                        __nv_bfloat162 vl; vl.x = l0; vl.y = l1;
                        *(__nv_bfloat162*)(hiN + eo) = vh;
                        *(__nv_bfloat162*)(loN + eo) = vl;
                    }
                }
        }
        tgt += 128;
        grid_sync(tgt);   // all h_new tiles visible

        // ===== fc: [128 x 16] over K=512 (h_new), 8 chunks, dbl-buffered =====
        float f0[2][4];
        #pragma unroll
        for (int t = 0; t < 2; ++t)
            #pragma unroll
            for (int k = 0; k < 4; ++k) f0[t][k] = 0.f;

        #define STAGE_FC(c, b) do {                                                \
            const char* Ah_ = (const char*)&d_Act[nxt][mb][0][(c)][0];             \
            const char* Al_ = (const char*)&d_Act[nxt][mb][1][(c)][0];             \
            uint32_t AB_ = smb + SM_A + (b) * 32768;                               \
            _Pragma("unroll")                                                      \
            for (int r_ = 0; r_ < 4; ++r_) {                                       \
                int u_ = tid + r_ * NTH;                                           \
                cpa16(AB_ + u_ * 16, Ah_ + u_ * 16);                               \
                cpa16(AB_ + 16384 + u_ * 16, Al_ + u_ * 16);                       \
            }                                                                      \
            uint32_t BB_ = smb + SM_B + (b) * 49152;                               \
            int t_ = tid >> 7, u_ = tid & 127;                                     \
            const char* src_ = (const char*)&d_Wf[cb][t_][(c)][0];                 \
            cpa16(BB_ + t_ * 2048 + u_ * 16, src_ + u_ * 16);                      \
        } while (0)

        STAGE_FC(0, 0);
        CP_COMMIT();
        #pragma unroll 1
        for (int c = 0; c < 8; ++c) {
            if (c < 7) { STAGE_FC(c + 1, (c + 1) & 1); CP_COMMIT(); CP_WAIT1(); }
            else       { CP_WAIT0(); }
            __syncthreads();
            const uint32_t AB = smb + SM_A + (c & 1) * 32768;
            const uint32_t BB = smb + SM_B + (c & 1) * 49152;
            #pragma unroll
            for (int q = 0; q < 4; ++q) {
                uint32_t ah[4], al[4], bb[4];
                ldsm4(ah, a_addr(AB, wid * 16, q, lane));
                ldsm4(al, a_addr(AB + 16384, wid * 16, q, lane));
                ldsm4(bb, b_addr(BB, 0, q, lane));          // hi, 2 n8 tiles
                mmabf(f0[0], ah, bb); mmabf(f0[1], ah, bb + 2);
                mmabf(f0[0], al, bb); mmabf(f0[1], al, bb + 2);
                ldsm4(bb, b_addr(BB + 2048, 0, q, lane));   // lo
                mmabf(f0[0], ah, bb); mmabf(f0[1], ah, bb + 2);
            }
            __syncthreads();
        }

        // ===== fc epilogue: x_new cols cb*16+[0,16) -> out + x tiles =====
        {
            const int trow = Tlen - 1 - s;   // reference reverses time at the end
            const int xc = 8 + (cb >> 2);
            char* xhi = (char*)&d_Act[nxt][mb][0][xc][0];
            char* xlo = (char*)&d_Act[nxt][mb][1][xc][0];
            #pragma unroll
            for (int nt = 0; nt < 2; ++nt) {
                const int col = nt * 8 + 2 * (lane & 3);
                #pragma unroll
                for (int ms = 0; ms < 2; ++ms) {
                    const int m_ = wid * 16 + (lane >> 2) + ms * 8;
                    float x0 = f0[nt][ms * 2]     + s_fb[col];
                    float x1 = f0[nt][ms * 2 + 1] + s_fb[col + 1];
                    *(float2*)&out[((size_t)(mb * 128 + m_) * Tlen + trow) * 128 +
                                   cb * 16 + col] = make_float2(x0, x1);
                    const int kk = (cb & 3) * 16 + col;
                    const int eo = tile_off(m_, kk);
                    __nv_bfloat16 q0, l0, q1, l1;
                    bsplit(x0, q0, l0); bsplit(x1, q1, l1);
                    __nv_bfloat162 vh; vh.x = q0; vh.y = q1;
                    __nv_bfloat162 vl; vl.x = l0; vl.y = l1;
                    *(__nv_bfloat162*)(xhi + eo) = vh;
                    *(__nv_bfloat162*)(xlo + eo) = vl;
                }
            }
        }
        tgt += 128;
        grid_sync(tgt);   // x tiles visible before next step
    }
}

extern "C" void kernel_launch(void* const* d_in, const int* in_sizes, int n_in,
                              void* d_out, int out_size) {
    const float* hidden = (const float*)d_in[0];
    const float* w_ih   = (const float*)d_in[1];
    const float* w_hh   = (const float*)d_in[2];
    const float* b_ih   = (const float*)d_in[3];
    const float* b_hh   = (const float*)d_in[4];
    const float* fc_w   = (const float*)d_in[5];
    const float* fc_b   = (const float*)d_in[6];
    float* out = (float*)d_out;

    setup_weights<<<1024, 256>>>(w_ih, w_hh, fc_w);
    setup_state<<<1024, 256>>>(hidden);

    cudaFuncSetAttribute(gru_main, cudaFuncAttributeMaxDynamicSharedMemorySize, SMTOT);
    gru_main<<<128, NTH, SMTOT>>>(b_ih, b_hh, fc_b, out);
}